// round 1
// baseline (speedup 1.0000x reference)
#include <cuda_runtime.h>
#include <cuda_bf16.h>

// Problem constants (fixed by the dataset)
#define NN 10000      // num nodes
#define EE 640000     // num edges
#define DD 128        // feature dim (in == out)

// Scratch (no cudaMalloc allowed)
__device__ float g_deg[NN];
__device__ float g_dis[NN];
__device__ float g_msg[NN * DD];   // g = (x@W) * dis[row]

// ---------------------------------------------------------------------------
// Kernel 1: init deg=1 (self loop) and zero the output accumulator
// ---------------------------------------------------------------------------
__global__ void k_init(float* __restrict__ out, int n, int nd) {
    int idx = blockIdx.x * blockDim.x + threadIdx.x;
    int stride = gridDim.x * blockDim.x;
    for (int i = idx; i < nd; i += stride) out[i] = 0.0f;
    for (int i = idx; i < n; i += stride) g_deg[i] = 1.0f;
}

// ---------------------------------------------------------------------------
// Kernel 2: degree over `row` (edge_index[0])
// ---------------------------------------------------------------------------
__global__ void k_deg(const int* __restrict__ row, int e) {
    int idx = blockIdx.x * blockDim.x + threadIdx.x;
    if (idx < e) atomicAdd(&g_deg[row[idx]], 1.0f);
}

// ---------------------------------------------------------------------------
// Kernel 3: dis = deg^{-1/2} (deg >= 1 always, no inf handling needed)
// ---------------------------------------------------------------------------
__global__ void k_dis(int n) {
    int idx = blockIdx.x * blockDim.x + threadIdx.x;
    if (idx < n) g_dis[idx] = rsqrtf(g_deg[idx]);
}

// ---------------------------------------------------------------------------
// Kernel 4: fused GEMM + row scale:  g_msg[i,:] = (x[i,:] @ W) * dis[i]
// Block = 128 threads, handles 8 rows. x tile in smem (float4), W from
// global (64KB, fully L2-resident + L1 hits, coalesced across threads).
// ---------------------------------------------------------------------------
#define ROWS_PER_BLOCK 8
__global__ __launch_bounds__(128) void k_gemm(const float* __restrict__ x,
                                              const float* __restrict__ W,
                                              int n) {
    __shared__ float4 xs[ROWS_PER_BLOCK][DD / 4];
    const int j = threadIdx.x;          // output column 0..127
    const int r0 = blockIdx.x * ROWS_PER_BLOCK;

    // cooperative load of 8 rows of x (8*32 float4 = 256, 2 per thread)
    const float4* x4 = (const float4*)x;
#pragma unroll
    for (int i = 0; i < 2; i++) {
        int idx = j + i * 128;          // 0..255
        int r = idx >> 5;               // 0..7
        int c = idx & 31;               // 0..31
        int gr = r0 + r;
        xs[r][c] = (gr < n) ? x4[gr * (DD / 4) + c]
                            : make_float4(0.f, 0.f, 0.f, 0.f);
    }
    __syncthreads();

    float acc[ROWS_PER_BLOCK];
#pragma unroll
    for (int r = 0; r < ROWS_PER_BLOCK; r++) acc[r] = 0.0f;

#pragma unroll 4
    for (int k = 0; k < DD; k += 4) {
        float w0 = W[(k + 0) * DD + j];
        float w1 = W[(k + 1) * DD + j];
        float w2 = W[(k + 2) * DD + j];
        float w3 = W[(k + 3) * DD + j];
#pragma unroll
        for (int r = 0; r < ROWS_PER_BLOCK; r++) {
            float4 xv = xs[r][k >> 2];
            acc[r] = fmaf(xv.x, w0, acc[r]);
            acc[r] = fmaf(xv.y, w1, acc[r]);
            acc[r] = fmaf(xv.z, w2, acc[r]);
            acc[r] = fmaf(xv.w, w3, acc[r]);
        }
    }

#pragma unroll
    for (int r = 0; r < ROWS_PER_BLOCK; r++) {
        int gr = r0 + r;
        if (gr < n) g_msg[gr * DD + j] = acc[r] * g_dis[gr];
    }
}

// ---------------------------------------------------------------------------
// Kernel 5: scatter.  One warp per edge; lane l moves floats [4l, 4l+4).
// out[col[e], :] += g_msg[row[e], :]
// ---------------------------------------------------------------------------
__global__ __launch_bounds__(256) void k_scatter(const int* __restrict__ row,
                                                 const int* __restrict__ col,
                                                 float* __restrict__ out,
                                                 int e) {
    int gtid = blockIdx.x * blockDim.x + threadIdx.x;
    int eidx = gtid >> 5;
    int lane = gtid & 31;
    if (eidx >= e) return;
    int r = __ldg(&row[eidx]);
    int c = __ldg(&col[eidx]);
    const float4 gv = *(const float4*)(g_msg + r * DD + lane * 4);
    float* dst = out + c * DD + lane * 4;
    atomicAdd(dst + 0, gv.x);
    atomicAdd(dst + 1, gv.y);
    atomicAdd(dst + 2, gv.z);
    atomicAdd(dst + 3, gv.w);
}

// ---------------------------------------------------------------------------
// Kernel 6: finalize: out[i,j] = dis[i]*(accum[i,j] + g_msg[i,j]) + bias[j]
// (self-loop contribution = g_msg[i]*dis[i] = h[i]*dis[i]^2)
// ---------------------------------------------------------------------------
__global__ void k_final(float* __restrict__ out,
                        const float* __restrict__ bias, int nd) {
    int idx = blockIdx.x * blockDim.x + threadIdx.x;
    if (idx >= nd) return;
    int i = idx >> 7;       // / 128
    int j = idx & 127;
    out[idx] = g_dis[i] * (out[idx] + g_msg[idx]) + bias[j];
}

// ---------------------------------------------------------------------------
extern "C" void kernel_launch(void* const* d_in, const int* in_sizes, int n_in,
                              void* d_out, int out_size) {
    const float* x    = (const float*)d_in[0];
    const int*   ei   = (const int*)d_in[1];
    const float* W    = (const float*)d_in[2];
    const float* bias = (const float*)d_in[3];
    float* out = (float*)d_out;

    const int n = in_sizes[0] / DD;   // 10000
    const int e = in_sizes[1] / 2;    // 640000
    const int nd = n * DD;

    const int* row = ei;        // edge_index[0]
    const int* col = ei + e;    // edge_index[1]

    k_init<<<512, 256>>>(out, n, nd);
    k_deg<<<(e + 255) / 256, 256>>>(row, e);
    k_dis<<<(n + 255) / 256, 256>>>(n);
    k_gemm<<<(n + ROWS_PER_BLOCK - 1) / ROWS_PER_BLOCK, 128>>>(x, W, n);
    {
        long long threads = (long long)e * 32;
        int blocks = (int)((threads + 255) / 256);
        k_scatter<<<blocks, 256>>>(row, col, out, e);
    }
    k_final<<<(nd + 255) / 256, 256>>>(out, bias, nd);
}

// round 2
// speedup vs baseline: 2.3160x; 2.3160x over previous
#include <cuda_runtime.h>
#include <cuda_bf16.h>

#define NN 10000      // num nodes (dataset-fixed)
#define EE 640000     // num edges
#define DD 128        // feature dim

// ---- scratch (__device__ globals; no cudaMalloc allowed) -------------------
__device__ int   g_degcnt[NN];       // out-degree counts (over row)
__device__ int   g_colcnt[NN];       // in-degree counts (over col)
__device__ int   g_off[NN + 1];      // CSR offsets by col
__device__ int   g_cursor[NN];       // scatter cursors
__device__ int   g_srow[EE];         // row[] sorted by col
__device__ float g_dis[NN];          // deg^{-1/2}
__device__ float g_msg[NN * DD];     // (x@W) * dis[row]

// ---------------------------------------------------------------------------
// K1: zero histograms
// ---------------------------------------------------------------------------
__global__ void k_zero(int n) {
    int i = blockIdx.x * blockDim.x + threadIdx.x;
    if (i < n) { g_degcnt[i] = 0; g_colcnt[i] = 0; }
}

// ---------------------------------------------------------------------------
// K2: histograms over row (degree) and col (CSR counts)
// ---------------------------------------------------------------------------
__global__ void k_hist(const int* __restrict__ row,
                       const int* __restrict__ col, int e) {
    int i = blockIdx.x * blockDim.x + threadIdx.x;
    if (i < e) {
        atomicAdd(&g_degcnt[row[i]], 1);
        atomicAdd(&g_colcnt[col[i]], 1);
    }
}

// ---------------------------------------------------------------------------
// K3: single-block exclusive scan of colcnt -> offsets/cursor; dis = rsqrt(deg+1)
// ---------------------------------------------------------------------------
__global__ __launch_bounds__(1024) void k_scan(int n) {
    __shared__ int sums[1024];
    const int t = threadIdx.x;
    const int chunk = (n + 1023) / 1024;
    const int beg = t * chunk;
    const int end = min(beg + chunk, n);

    int s = 0;
    for (int i = beg; i < end; i++) s += g_colcnt[i];
    sums[t] = s;
    __syncthreads();

    // Hillis-Steele inclusive scan (read-all then write-all each step)
    for (int off = 1; off < 1024; off <<= 1) {
        int v = (t >= off) ? sums[t - off] : 0;
        __syncthreads();
        sums[t] += v;
        __syncthreads();
    }

    int run = (t == 0) ? 0 : sums[t - 1];
    for (int i = beg; i < end; i++) {
        g_off[i]    = run;
        g_cursor[i] = run;
        run += g_colcnt[i];
    }
    if (end == n && beg <= n) g_off[n] = run;

    for (int i = t; i < n; i += 1024)
        g_dis[i] = rsqrtf((float)(g_degcnt[i] + 1));  // +1 self-loop
}

// ---------------------------------------------------------------------------
// K4: counting-sort scatter: srow sorted by col
// ---------------------------------------------------------------------------
__global__ void k_sort(const int* __restrict__ row,
                       const int* __restrict__ col, int e) {
    int i = blockIdx.x * blockDim.x + threadIdx.x;
    if (i < e) {
        int pos = atomicAdd(&g_cursor[col[i]], 1);
        g_srow[pos] = row[i];
    }
}

// ---------------------------------------------------------------------------
// K5: fused GEMM + row scale:  g_msg[i,:] = (x[i,:] @ W) * dis[i]
// 16 rows per 128-thread block; x tile in smem, W streamed (L1/L2 resident).
// ---------------------------------------------------------------------------
#define RPB 16
__global__ __launch_bounds__(128) void k_gemm(const float* __restrict__ x,
                                              const float* __restrict__ W,
                                              int n) {
    __shared__ float4 xs[RPB][DD / 4];
    const int j  = threadIdx.x;              // output column
    const int r0 = blockIdx.x * RPB;

    const float4* x4 = (const float4*)x;
#pragma unroll
    for (int i = 0; i < RPB * (DD / 4) / 128; i++) {   // 4 float4 per thread
        int idx = j + i * 128;
        int r = idx >> 5, c = idx & 31;
        int gr = r0 + r;
        xs[r][c] = (gr < n) ? x4[gr * (DD / 4) + c]
                            : make_float4(0.f, 0.f, 0.f, 0.f);
    }
    __syncthreads();

    float acc[RPB];
#pragma unroll
    for (int r = 0; r < RPB; r++) acc[r] = 0.0f;

#pragma unroll 4
    for (int k = 0; k < DD; k += 4) {
        float w0 = W[(k + 0) * DD + j];
        float w1 = W[(k + 1) * DD + j];
        float w2 = W[(k + 2) * DD + j];
        float w3 = W[(k + 3) * DD + j];
#pragma unroll
        for (int r = 0; r < RPB; r++) {
            float4 xv = xs[r][k >> 2];
            acc[r] = fmaf(xv.x, w0, acc[r]);
            acc[r] = fmaf(xv.y, w1, acc[r]);
            acc[r] = fmaf(xv.z, w2, acc[r]);
            acc[r] = fmaf(xv.w, w3, acc[r]);
        }
    }

#pragma unroll
    for (int r = 0; r < RPB; r++) {
        int gr = r0 + r;
        if (gr < n) g_msg[gr * DD + j] = acc[r] * g_dis[gr];
    }
}

// ---------------------------------------------------------------------------
// K6: gather-reduce + finalize. One warp per node; lane l owns dims [4l,4l+4).
// out[i,:] = dis[i] * (sum_{e: col=i} g_msg[srow[e],:] + g_msg[i,:]) + bias
// ---------------------------------------------------------------------------
__global__ __launch_bounds__(256) void k_reduce(float* __restrict__ out,
                                                const float* __restrict__ bias,
                                                int n) {
    const int node = blockIdx.x * 8 + (threadIdx.x >> 5);
    const int lane = threadIdx.x & 31;
    if (node >= n) return;

    const float4* msg4 = (const float4*)g_msg;
    const int beg = g_off[node];
    const int end = g_off[node + 1];

    float4 acc = msg4[node * 32 + lane];          // self-loop term
    int e = beg;
    for (; e + 4 <= end; e += 4) {
        int r0 = g_srow[e + 0];
        int r1 = g_srow[e + 1];
        int r2 = g_srow[e + 2];
        int r3 = g_srow[e + 3];
        float4 v0 = msg4[r0 * 32 + lane];
        float4 v1 = msg4[r1 * 32 + lane];
        float4 v2 = msg4[r2 * 32 + lane];
        float4 v3 = msg4[r3 * 32 + lane];
        acc.x += (v0.x + v1.x) + (v2.x + v3.x);
        acc.y += (v0.y + v1.y) + (v2.y + v3.y);
        acc.z += (v0.z + v1.z) + (v2.z + v3.z);
        acc.w += (v0.w + v1.w) + (v2.w + v3.w);
    }
    for (; e < end; e++) {
        float4 v = msg4[g_srow[e] * 32 + lane];
        acc.x += v.x; acc.y += v.y; acc.z += v.z; acc.w += v.w;
    }

    const float s = g_dis[node];
    const float4 b = ((const float4*)bias)[lane];
    float4 o;
    o.x = fmaf(s, acc.x, b.x);
    o.y = fmaf(s, acc.y, b.y);
    o.z = fmaf(s, acc.z, b.z);
    o.w = fmaf(s, acc.w, b.w);
    ((float4*)out)[node * 32 + lane] = o;
}

// ---------------------------------------------------------------------------
extern "C" void kernel_launch(void* const* d_in, const int* in_sizes, int n_in,
                              void* d_out, int out_size) {
    const float* x    = (const float*)d_in[0];
    const int*   ei   = (const int*)d_in[1];
    const float* W    = (const float*)d_in[2];
    const float* bias = (const float*)d_in[3];
    float* out = (float*)d_out;

    const int n = in_sizes[0] / DD;   // 10000
    const int e = in_sizes[1] / 2;    // 640000

    const int* row = ei;              // edge_index[0]
    const int* col = ei + e;          // edge_index[1]

    k_zero<<<(n + 255) / 256, 256>>>(n);
    k_hist<<<(e + 255) / 256, 256>>>(row, col, e);
    k_scan<<<1, 1024>>>(n);
    k_sort<<<(e + 255) / 256, 256>>>(row, col, e);
    k_gemm<<<(n + RPB - 1) / RPB, 128>>>(x, W, n);
    k_reduce<<<(n + 7) / 8, 256>>>(out, bias, n);
}